// round 17
// baseline (speedup 1.0000x reference)
#include <cuda_runtime.h>

// SGC: out = S^2 (X w) + b,  S = D^-1/2 (A+I) D^-1/2.
// Propagate ONE scalar per node; factor dis[c] out of the edge loop:
//   t[c]  = sum_edges z[r],  z = dis*y
//   y1    = dis*t1 + y0/deg
//   out   = dis*(t2 + dis*y1) + b
// Two launches: (1) fused deg-count/pair-pack + dot kernel, (2) persistent
// kernel running prep -> pass1 -> mid -> pass2 -> final with software grid
// barriers.  degcnt/t1/t2 are zero at rest (BSS + reset in final phase).

#define NN 100000
#define EE 600000
#define DD 128
#define TB 256
#define EDGE_BLOCKS ((EE + TB - 1) / TB)          // 2344
#define DOT_BLOCKS  ((NN / 8 * 32 + TB - 1) / TB) // 1563 (8 nodes/warp)
#define MAX_PGRID   1184                          // 148 SMs * 8 blocks (256 thr)

__device__ int      g_degcnt[NN];  // zero at rest
__device__ float    g_dis[NN];
__device__ float    g_y0[NN];
__device__ float    g_z0[NN];      // dis * y0
__device__ float    g_y1s[NN];     // y0 / deg
__device__ float    g_z1[NN];      // dis * y1
__device__ float    g_t1[NN];      // zero at rest
__device__ float    g_t2[NN];      // zero at rest
__device__ int2     g_pairs[EE];   // packed (row, col) — L2-resident
__device__ unsigned g_bar_count;   // zero at rest
__device__ unsigned g_bar_gen;     // monotonically increasing across calls

// ---------------------------------------------------------------------------
// Launch 1: dot blocks FIRST (long, DRAM-bound); edge blocks fill in.
__global__ void __launch_bounds__(TB) k_deg_dot(const void* __restrict__ ei,
                                                const float* __restrict__ x,
                                                const float* __restrict__ W) {
    if (blockIdx.x >= DOT_BLOCKS) {
        // ---- edge part: sniff dtype, pack pair, count degree ----
        int e = (blockIdx.x - DOT_BLOCKS) * TB + threadIdx.x;
        if (e >= EE) return;
        // int32 data viewed as int64 puts a random node index in the high
        // word; 16 consecutive in-range int64s => genuinely int64 (~1e-80 fp).
        const long long* p64 = (const long long*)ei;
        int is64 = 1;
        #pragma unroll
        for (int k = 0; k < 16; k++) {
            long long v = p64[k];
            if (v < 0 || v >= (long long)NN) is64 = 0;
        }
        int r, c;
        if (is64) { r = (int)p64[e]; c = (int)p64[EE + e]; }
        else      { const int* p32 = (const int*)ei; r = p32[e]; c = p32[EE + e]; }
        g_pairs[e] = make_int2(r, c);
        atomicAdd(&g_degcnt[c], 1);
        return;
    }
    // ---- dot part: 8 nodes per warp, 8 front-batched float4 loads ----
    int t = blockIdx.x * TB + threadIdx.x;
    int warp = t >> 5;
    int lane = t & 31;
    int base = warp * 8;                 // NN % 8 == 0
    if (base >= NN) return;
    float4 wv = __ldg(((const float4*)W) + lane);

    float4 xv[8];
    #pragma unroll
    for (int j = 0; j < 8; j++)
        xv[j] = __ldg(((const float4*)(x + (size_t)(base + j) * DD)) + lane);

    float s0 = xv[0].x * wv.x + xv[0].y * wv.y + xv[0].z * wv.z + xv[0].w * wv.w;
    float s1 = xv[1].x * wv.x + xv[1].y * wv.y + xv[1].z * wv.z + xv[1].w * wv.w;
    float s2 = xv[2].x * wv.x + xv[2].y * wv.y + xv[2].z * wv.z + xv[2].w * wv.w;
    float s3 = xv[3].x * wv.x + xv[3].y * wv.y + xv[3].z * wv.z + xv[3].w * wv.w;
    float s4 = xv[4].x * wv.x + xv[4].y * wv.y + xv[4].z * wv.z + xv[4].w * wv.w;
    float s5 = xv[5].x * wv.x + xv[5].y * wv.y + xv[5].z * wv.z + xv[5].w * wv.w;
    float s6 = xv[6].x * wv.x + xv[6].y * wv.y + xv[6].z * wv.z + xv[6].w * wv.w;
    float s7 = xv[7].x * wv.x + xv[7].y * wv.y + xv[7].z * wv.z + xv[7].w * wv.w;

    #pragma unroll
    for (int o = 16; o; o >>= 1) {
        s0 += __shfl_xor_sync(0xffffffffu, s0, o);
        s1 += __shfl_xor_sync(0xffffffffu, s1, o);
        s2 += __shfl_xor_sync(0xffffffffu, s2, o);
        s3 += __shfl_xor_sync(0xffffffffu, s3, o);
        s4 += __shfl_xor_sync(0xffffffffu, s4, o);
        s5 += __shfl_xor_sync(0xffffffffu, s5, o);
        s6 += __shfl_xor_sync(0xffffffffu, s6, o);
        s7 += __shfl_xor_sync(0xffffffffu, s7, o);
    }

    if (lane < 8) {
        float lo = (lane & 2) ? ((lane & 1) ? s3 : s2) : ((lane & 1) ? s1 : s0);
        float hi = (lane & 2) ? ((lane & 1) ? s7 : s6) : ((lane & 1) ? s5 : s4);
        g_y0[base + lane] = (lane & 4) ? hi : lo;
    }
}

// ---------------------------------------------------------------------------
// Software grid barrier (sense-reversing on a generation counter).  All
// blocks are wave-1 resident: grid sized from the occupancy API and clamped.
__device__ __forceinline__ void gbar(int nblocks) {
    __syncthreads();
    if (threadIdx.x == 0) {
        __threadfence();                               // publish phase writes
        unsigned gen = *(volatile unsigned*)&g_bar_gen;
        unsigned arr = atomicAdd(&g_bar_count, 1u);
        if (arr == (unsigned)nblocks - 1) {
            g_bar_count = 0;
            __threadfence();                           // count reset before release
            *(volatile unsigned*)&g_bar_gen = gen + 1;
        } else {
            while (*(volatile unsigned*)&g_bar_gen == gen) { __nanosleep(32); }
        }
        __threadfence();                               // acquire
    }
    __syncthreads();
}

// Persistent kernel: prep -> pass1 -> mid -> pass2 -> final(+reset).
__global__ void __launch_bounds__(TB) k_persist(float* __restrict__ out,
                                                const float* __restrict__ b) {
    const int tid    = blockIdx.x * TB + threadIdx.x;
    const int stride = gridDim.x * TB;
    const int nb     = gridDim.x;

    // Phase 1: prep — finalize per-node normalization
    for (int i = tid; i < NN; i += stride) {
        float deg = (float)(1 + g_degcnt[i]);          // +1 = self loop
        float y0  = g_y0[i];
        float dis = rsqrtf(deg);
        g_dis[i] = dis;
        g_z0[i]  = dis * y0;
        g_y1s[i] = y0 / deg;
    }
    gbar(nb);

    // Phase 2: pass1 — t1[c] += z0[r]
    for (int e = tid; e < EE; e += stride) {
        int2 p = g_pairs[e];
        atomicAdd(&g_t1[p.y], __ldg(&g_z0[p.x]));
    }
    gbar(nb);

    // Phase 3: mid — z1 = dis*(dis*t1 + y0/deg)
    for (int i = tid; i < NN; i += stride) {
        float dis = g_dis[i];
        g_z1[i] = dis * (dis * g_t1[i] + g_y1s[i]);
    }
    gbar(nb);

    // Phase 4: pass2 — t2[c] += z1[r]
    for (int e = tid; e < EE; e += stride) {
        int2 p = g_pairs[e];
        atomicAdd(&g_t2[p.y], __ldg(&g_z1[p.x]));
    }
    gbar(nb);

    // Phase 5: final — out = dis*(t2 + z1) + b; reset persistent state
    float bias = b[0];
    for (int i = tid; i < NN; i += stride) {
        out[i] = g_dis[i] * (g_t2[i] + g_z1[i]) + bias;
        g_degcnt[i] = 0;
        g_t1[i] = 0.0f;
        g_t2[i] = 0.0f;
    }
}

// ---------------------------------------------------------------------------
extern "C" void kernel_launch(void* const* d_in, const int* in_sizes, int n_in,
                              void* d_out, int out_size) {
    const float* x  = (const float*)d_in[0];
    const void*  ei = d_in[1];
    const float* W  = (const float*)d_in[2];
    const float* b  = (const float*)d_in[3];
    float* out = (float*)d_out;

    // Size the persistent grid so every block is wave-1 resident.
    int dev = 0, sms = 0, bpm = 0;
    cudaGetDevice(&dev);
    cudaDeviceGetAttribute(&sms, cudaDevAttrMultiProcessorCount, dev);
    cudaOccupancyMaxActiveBlocksPerMultiprocessor(&bpm, k_persist, TB, 0);
    if (sms <= 0) sms = 148;
    if (bpm <= 0) bpm = 4;
    long long want = (long long)sms * bpm;
    int pgrid = (want > MAX_PGRID) ? MAX_PGRID : (int)want;

    k_deg_dot<<<DOT_BLOCKS + EDGE_BLOCKS, TB>>>(ei, x, W);
    k_persist<<<pgrid, TB>>>(out, b);
}